// round 1
// baseline (speedup 1.0000x reference)
#include <cuda_runtime.h>
#include <cuda_bf16.h>

#define BATCH 32
#define NBOX 300
#define HH 1024
#define WW 1024
#define NTOT (BATCH * NBOX)            /* 9600 */
#define ROWS_PER_BLK 16
#define NCHUNK (HH / ROWS_PER_BLK)     /* 64 */
#define NTHREADS 256
#define NWARPS (NTHREADS / 32)
#define RED_BLOCKS ((NTOT + NTHREADS - 1) / NTHREADS)  /* 38 */

// Scratch (allocation-free: device globals)
__device__ int4  g_box[NTOT];                 // x1, x2, y1, y2
__device__ float g_wt[NTOT];                  // valid ? conf/area : 0
__device__ float g_partial[NCHUNK * NTOT];    // per-chunk per-box partial sums (2.4 MB)
__device__ float g_blk[RED_BLOCKS];

// ---------------------------------------------------------------------------
// Kernel 1: per-box metadata (trunc-toward-zero + clamp exactly like reference)
// ---------------------------------------------------------------------------
__global__ void setup_kernel(const float* __restrict__ boxes,
                             const float* __restrict__ conf) {
    int i = blockIdx.x * blockDim.x + threadIdx.x;
    if (i >= NTOT) return;
    float cx = boxes[i * 4 + 0];
    float cy = boxes[i * 4 + 1];
    float w  = boxes[i * 4 + 2];
    float h  = boxes[i * 4 + 3];
    float c  = conf[i];

    // (int) cast truncates toward zero == jnp.trunc().astype(int32)
    int x1 = (int)((cx - 0.5f * w) * (float)WW);
    int x2 = (int)((cx + 0.5f * w) * (float)WW);
    int y1 = (int)((cy - 0.5f * h) * (float)HH);
    int y2 = (int)((cy + 0.5f * h) * (float)HH);
    x1 = min(max(x1, 0), WW - 1);
    x2 = min(max(x2, 0), WW - 1);
    y1 = min(max(y1, 0), HH - 1);
    y2 = min(max(y2, 0), HH - 1);

    bool valid = (c >= 0.3f) && (x2 > x1) && (y2 > y1);
    float area = (float)((y2 - y1) * (x2 - x1));
    g_box[i] = make_int4(x1, x2, y1, y2);
    g_wt[i]  = valid ? (c / area) : 0.0f;   // area > 0 whenever valid
}

// ---------------------------------------------------------------------------
// Kernel 2: fused difference + row prefix-scan + box accumulation.
// grid = (NCHUNK, BATCH); block = 256. Each block handles 16 rows of one batch.
// ---------------------------------------------------------------------------
__global__ __launch_bounds__(NTHREADS)
void main_kernel(const float* __restrict__ seg) {
    __shared__ __align__(16) float P[WW];   // exclusive prefix of D along the row
    __shared__ float wsum[NWARPS];

    const int t    = threadIdx.x;
    const int lane = t & 31;
    const int wid  = t >> 5;
    const int b     = blockIdx.y;
    const int chunk = blockIdx.x;
    const int y0    = chunk * ROWS_PER_BLK;
    const int base  = b * NBOX;

    // Each thread owns up to 2 boxes (300 boxes, 256 threads)
    const int j0 = t, j1 = t + NTHREADS;
    int4 bx0 = (j0 < NBOX) ? g_box[base + j0] : make_int4(0, 0, 0, 0);
    int4 bx1 = (j1 < NBOX) ? g_box[base + j1] : make_int4(0, 0, 0, 0);
    float a0 = 0.0f, a1 = 0.0f;

    const float4* __restrict__ drv =
        (const float4*)(seg + ((size_t)(b * 3 + 1) * HH + y0) * WW);
    const float4* __restrict__ fot =
        (const float4*)(seg + ((size_t)(b * 3 + 2) * HH + y0) * WW);

    for (int r = 0; r < ROWS_PER_BLK; ++r) {
        const int y = y0 + r;
        float4 dv = drv[r * (WW / 4) + t];
        float4 fv = fot[r * (WW / 4) + t];
        float d0 = fv.x - dv.x;
        float d1 = fv.y - dv.y;
        float d2 = fv.z - dv.z;
        float d3 = fv.w - dv.w;
        // thread-local inclusive prefixes
        float s0 = d0, s1 = s0 + d1, s2 = s1 + d2, s3 = s2 + d3;

        // warp inclusive scan of thread sums
        float v = s3;
        #pragma unroll
        for (int o = 1; o < 32; o <<= 1) {
            float n = __shfl_up_sync(0xffffffffu, v, o);
            if (lane >= o) v += n;
        }
        if (lane == 31) wsum[wid] = v;
        __syncthreads();

        float woff = 0.0f;
        #pragma unroll
        for (int i2 = 0; i2 < NWARPS; ++i2)
            if (i2 < wid) woff += wsum[i2];

        float ex = woff + (v - s3);  // exclusive prefix before this thread's 4 elems
        ((float4*)P)[t] = make_float4(ex, ex + s0, ex + s1, ex + s2);
        __syncthreads();

        // box sum over cols [x1, x2) of this row = P[x2] - P[x1]
        if (y >= bx0.z && y < bx0.w) a0 += P[bx0.y] - P[bx0.x];
        if (y >= bx1.z && y < bx1.w) a1 += P[bx1.y] - P[bx1.x];
        __syncthreads();  // protect P and wsum before next row
    }

    if (j0 < NBOX) g_partial[chunk * NTOT + base + j0] = a0;
    if (j1 < NBOX) g_partial[chunk * NTOT + base + j1] = a1;
}

// ---------------------------------------------------------------------------
// Kernel 3: per-box chunk reduction + relu*weight, block partial sums
// ---------------------------------------------------------------------------
__global__ void reduce1_kernel() {
    int i = blockIdx.x * blockDim.x + threadIdx.x;
    float val = 0.0f;
    if (i < NTOT) {
        float s = 0.0f;
        #pragma unroll 8
        for (int c = 0; c < NCHUNK; ++c)
            s += g_partial[c * NTOT + i];
        val = fmaxf(s, 0.0f) * g_wt[i];
    }
    // block reduction
    __shared__ float red[NWARPS];
    #pragma unroll
    for (int o = 16; o; o >>= 1) val += __shfl_down_sync(0xffffffffu, val, o);
    if ((threadIdx.x & 31) == 0) red[threadIdx.x >> 5] = val;
    __syncthreads();
    if (threadIdx.x < 32) {
        float v = (threadIdx.x < NWARPS) ? red[threadIdx.x] : 0.0f;
        #pragma unroll
        for (int o = 16; o; o >>= 1) v += __shfl_down_sync(0xffffffffu, v, o);
        if (threadIdx.x == 0) g_blk[blockIdx.x] = v;
    }
}

// ---------------------------------------------------------------------------
// Kernel 4: final scalar
// ---------------------------------------------------------------------------
__global__ void reduce2_kernel(float* __restrict__ out) {
    float v = (threadIdx.x < RED_BLOCKS) ? g_blk[threadIdx.x] : 0.0f;
    #pragma unroll
    for (int o = 16; o; o >>= 1) v += __shfl_down_sync(0xffffffffu, v, o);
    __shared__ float s2[2];
    if ((threadIdx.x & 31) == 0) s2[threadIdx.x >> 5] = v;
    __syncthreads();
    if (threadIdx.x == 0) out[0] = (s2[0] + s2[1]) / (float)NTOT;
}

extern "C" void kernel_launch(void* const* d_in, const int* in_sizes, int n_in,
                              void* d_out, int out_size) {
    const float* boxes = (const float*)d_in[0];  // (32,300,4)
    const float* conf  = (const float*)d_in[1];  // (32,300)
    const float* seg   = (const float*)d_in[2];  // (32,3,1024,1024)

    setup_kernel<<<RED_BLOCKS, NTHREADS>>>(boxes, conf);
    dim3 grid(NCHUNK, BATCH);
    main_kernel<<<grid, NTHREADS>>>(seg);
    reduce1_kernel<<<RED_BLOCKS, NTHREADS>>>();
    reduce2_kernel<<<1, 64>>>((float*)d_out);
}

// round 2
// speedup vs baseline: 1.2541x; 1.2541x over previous
#include <cuda_runtime.h>

#define BATCH 32
#define NBOX 300
#define HH 1024
#define WW 1024
#define NTOT (BATCH * NBOX)            /* 9600 */
#define RPB 8                          /* rows per block, one per warp */
#define NCHUNK (HH / RPB)              /* 128 */
#define NT 256
#define RED_BLOCKS ((NTOT + NT - 1) / NT)  /* 38 */

// Scratch (allocation-free device globals)
__device__ float g_partial[NCHUNK * NTOT];   // 4.9 MB per-chunk box partials
__device__ float g_blk[RED_BLOCKS];
__device__ int   g_ctr = 0;

// trunc-toward-zero + clamp, exactly matching the reference
__device__ __forceinline__ int4 box_meta(const float4 bb) {
    int x1 = (int)((bb.x - 0.5f * bb.z) * (float)WW);
    int x2 = (int)((bb.x + 0.5f * bb.z) * (float)WW);
    int y1 = (int)((bb.y - 0.5f * bb.w) * (float)HH);
    int y2 = (int)((bb.y + 0.5f * bb.w) * (float)HH);
    x1 = min(max(x1, 0), WW - 1);
    x2 = min(max(x2, 0), WW - 1);
    y1 = min(max(y1, 0), HH - 1);
    y2 = min(max(y2, 0), HH - 1);
    return make_int4(x1, x2, y1, y2);
}

// ---------------------------------------------------------------------------
// Main kernel: warp-per-row fused diff + prefix scan + box accumulate.
// grid = (NCHUNK, BATCH), block = 256 (8 warps). One barrier per block.
// ---------------------------------------------------------------------------
__global__ __launch_bounds__(NT, 2)
void main_kernel(const float* __restrict__ seg, const float* __restrict__ boxes) {
    __shared__ __align__(16) float P[RPB][WW];   // 32 KB: exclusive row prefixes

    const int t    = threadIdx.x;
    const int lane = t & 31;
    const int wid  = t >> 5;
    const int b     = blockIdx.y;
    const int chunk = blockIdx.x;
    const int y0    = chunk * RPB;
    const int base  = b * NBOX;
    const int y     = y0 + wid;                  // this warp's row

    // Inline box metadata (boxes array is tiny -> L2 resident)
    const float4* __restrict__ bp = (const float4*)boxes;
    int4 bx0 = box_meta(bp[base + t]);           // t < 256 < 300 always valid
    int4 bx1 = (t + NT < NBOX) ? box_meta(bp[base + t + NT])
                               : make_int4(0, 0, 0, 0);

    const float4* __restrict__ drv =
        (const float4*)(seg + ((size_t)(b * 3 + 1) * HH + y) * WW);
    const float4* __restrict__ fot =
        (const float4*)(seg + ((size_t)(b * 3 + 2) * HH + y) * WW);

    // 16 back-to-back streaming LDG.128 per warp (max MLP)
    float4 dv[8], fv[8];
    #pragma unroll
    for (int i = 0; i < 8; ++i) {
        dv[i] = __ldcs(&drv[i * 32 + lane]);
        fv[i] = __ldcs(&fot[i * 32 + lane]);
    }

    // Cyclic exclusive prefix over the row, no block barrier needed.
    // Chunk c = i*32 + lane covers columns [4c, 4c+4).
    float carry = 0.0f;
    #pragma unroll
    for (int i = 0; i < 8; ++i) {
        float e0 = fv[i].x - dv[i].x;
        float e1 = fv[i].y - dv[i].y;
        float e2 = fv[i].z - dv[i].z;
        float e3 = fv[i].w - dv[i].w;
        float s0 = e0, s1 = s0 + e1, s2 = s1 + e2, s3 = s2 + e3;

        float v = s3;                            // warp inclusive scan of chunk sums
        #pragma unroll
        for (int o = 1; o < 32; o <<= 1) {
            float n = __shfl_up_sync(0xffffffffu, v, o);
            if (lane >= o) v += n;
        }
        float ex = carry + (v - s3);             // exclusive prefix before this chunk
        carry += __shfl_sync(0xffffffffu, v, 31);
        *(float4*)&P[wid][i * 128 + lane * 4] =
            make_float4(ex, ex + s0, ex + s1, ex + s2);
    }
    __syncthreads();                             // the ONLY barrier

    // Box accumulation: sum over cols [x1,x2) of row y = P[y][x2] - P[y][x1]
    float a0 = 0.0f, a1 = 0.0f;
    #pragma unroll
    for (int r = 0; r < RPB; ++r) {
        const int yy = y0 + r;
        if (yy >= bx0.z && yy < bx0.w) a0 += P[r][bx0.y] - P[r][bx0.x];
        if (yy >= bx1.z && yy < bx1.w) a1 += P[r][bx1.y] - P[r][bx1.x];
    }
    g_partial[chunk * NTOT + base + t] = a0;
    if (t + NT < NBOX) g_partial[chunk * NTOT + base + t + NT] = a1;
}

// ---------------------------------------------------------------------------
// Fused reduction: per-box chunk sum + relu*weight + grid reduction via
// last-block-done counter (deterministic: fixed-order final sum).
// ---------------------------------------------------------------------------
__global__ __launch_bounds__(NT)
void reduce_kernel(const float* __restrict__ boxes,
                   const float* __restrict__ conf,
                   float* __restrict__ out) {
    const int t = threadIdx.x;
    const int i = blockIdx.x * NT + t;

    float val = 0.0f;
    if (i < NTOT) {
        float s = 0.0f;
        #pragma unroll 8
        for (int c = 0; c < NCHUNK; ++c)
            s += g_partial[c * NTOT + i];
        float4 bb = ((const float4*)boxes)[i];
        int4 m = box_meta(bb);
        float cf = conf[i];
        bool valid = (cf >= 0.3f) && (m.y > m.x) && (m.w > m.z);
        float area = (float)((m.w - m.z) * (m.y - m.x));
        val = valid ? fmaxf(s, 0.0f) * (cf / area) : 0.0f;
    }

    // Block reduction
    __shared__ float red[NT / 32];
    #pragma unroll
    for (int o = 16; o; o >>= 1) val += __shfl_down_sync(0xffffffffu, val, o);
    if ((t & 31) == 0) red[t >> 5] = val;
    __syncthreads();
    if (t < 32) {
        float v = (t < NT / 32) ? red[t] : 0.0f;
        #pragma unroll
        for (int o = 4; o; o >>= 1) v += __shfl_down_sync(0xffffffffu, v, o);
        if (t == 0) g_blk[blockIdx.x] = v;
    }

    // Last-block-done grid reduction
    __shared__ int amLast;
    __threadfence();
    if (t == 0) amLast = (atomicAdd(&g_ctr, 1) == gridDim.x - 1);
    __syncthreads();
    if (amLast) {
        __threadfence();
        if (t < 32) {
            float v = g_blk[t];                       // t < 32 < 38: valid
            if (t + 32 < RED_BLOCKS) v += g_blk[t + 32];
            #pragma unroll
            for (int o = 16; o; o >>= 1) v += __shfl_down_sync(0xffffffffu, v, o);
            if (t == 0) {
                out[0] = v / (float)NTOT;
                g_ctr = 0;                            // reset for next graph replay
            }
        }
    }
}

extern "C" void kernel_launch(void* const* d_in, const int* in_sizes, int n_in,
                              void* d_out, int out_size) {
    const float* boxes = (const float*)d_in[0];  // (32,300,4)
    const float* conf  = (const float*)d_in[1];  // (32,300)
    const float* seg   = (const float*)d_in[2];  // (32,3,1024,1024)

    dim3 grid(NCHUNK, BATCH);
    main_kernel<<<grid, NT>>>(seg, boxes);
    reduce_kernel<<<RED_BLOCKS, NT>>>(boxes, conf, (float*)d_out);
}

// round 3
// speedup vs baseline: 1.4285x; 1.1390x over previous
#include <cuda_runtime.h>

#define BATCH 32
#define NBOX 300
#define HH 1024
#define WW 1024
#define NTOT (BATCH * NBOX)            /* 9600 */
#define RPB 8                          /* rows per warp-iteration (1 row/warp) */
#define GITER 8                        /* iterations per block */
#define BAND (RPB * GITER)             /* 64 rows per block */
#define CGROUPS (HH / BAND)            /* 16 */
#define NT 256
#define RED_BLOCKS ((NTOT + NT - 1) / NT)  /* 38 */

// Scratch (allocation-free device globals)
__device__ float g_partial[CGROUPS * NTOT];  // 614 KB -> L2-resident
__device__ float g_blk[RED_BLOCKS];
__device__ int   g_ctr = 0;

// trunc-toward-zero + clamp, exactly matching the reference
__device__ __forceinline__ int4 box_meta(const float4 bb) {
    int x1 = (int)((bb.x - 0.5f * bb.z) * (float)WW);
    int x2 = (int)((bb.x + 0.5f * bb.z) * (float)WW);
    int y1 = (int)((bb.y - 0.5f * bb.w) * (float)HH);
    int y2 = (int)((bb.y + 0.5f * bb.w) * (float)HH);
    x1 = min(max(x1, 0), WW - 1);
    x2 = min(max(x2, 0), WW - 1);
    y1 = min(max(y1, 0), HH - 1);
    y2 = min(max(y2, 0), HH - 1);
    return make_int4(x1, x2, y1, y2);
}

// ---------------------------------------------------------------------------
// Main kernel: persistent band of 64 rows per block.
// grid = (CGROUPS, BATCH), block = 256 (8 warps, one row each per iteration).
// Software pipeline: scan(g) -> sync -> issue loads(g+1) -> gather(g) -> sync.
// ---------------------------------------------------------------------------
__global__ __launch_bounds__(NT, 2)
void main_kernel(const float* __restrict__ seg, const float* __restrict__ boxes) {
    __shared__ __align__(16) float P[RPB][WW];   // 32 KB exclusive row prefixes

    const int t    = threadIdx.x;
    const int lane = t & 31;
    const int wid  = t >> 5;
    const int b    = blockIdx.y;
    const int Y0   = blockIdx.x * BAND;
    const int base = b * NBOX;

    // Inline box metadata (boxes array tiny -> L2 resident)
    const float4* __restrict__ bp = (const float4*)boxes;
    int4 bx0 = box_meta(bp[base + t]);                    // t < 256 < 300
    int4 bx1 = (t + NT < NBOX) ? box_meta(bp[base + t + NT])
                               : make_int4(0, 0, 0, 0);

    const float* segD = seg + (size_t)(b * 3 + 1) * HH * WW;
    const float* segF = seg + (size_t)(b * 3 + 2) * HH * WW;

    float4 dv[8], fv[8];

    // preload iteration 0: row Y0 + wid
    {
        const float4* dr = (const float4*)(segD + (size_t)(Y0 + wid) * WW);
        const float4* fr = (const float4*)(segF + (size_t)(Y0 + wid) * WW);
        #pragma unroll
        for (int i = 0; i < 8; ++i) {
            dv[i] = __ldcs(&dr[i * 32 + lane]);
            fv[i] = __ldcs(&fr[i * 32 + lane]);
        }
    }

    float a0 = 0.0f, a1 = 0.0f;

    for (int g = 0; g < GITER; ++g) {
        // ---- scan: row -> exclusive prefix in P[wid] (no block barrier) ----
        float carry = 0.0f;
        #pragma unroll
        for (int i = 0; i < 8; ++i) {
            float e0 = fv[i].x - dv[i].x;
            float e1 = fv[i].y - dv[i].y;
            float e2 = fv[i].z - dv[i].z;
            float e3 = fv[i].w - dv[i].w;
            float s0 = e0, s1 = s0 + e1, s2 = s1 + e2, s3 = s2 + e3;

            float v = s3;                        // warp inclusive scan of chunk sums
            #pragma unroll
            for (int o = 1; o < 32; o <<= 1) {
                float n = __shfl_up_sync(0xffffffffu, v, o);
                if (lane >= o) v += n;
            }
            float ex = carry + (v - s3);
            carry += __shfl_sync(0xffffffffu, v, 31);
            *(float4*)&P[wid][i * 128 + lane * 4] =
                make_float4(ex, ex + s0, ex + s1, ex + s2);
        }
        __syncthreads();

        // ---- issue next band's loads (in flight during gather) ----
        if (g + 1 < GITER) {
            const int yn = Y0 + (g + 1) * RPB + wid;
            const float4* dr = (const float4*)(segD + (size_t)yn * WW);
            const float4* fr = (const float4*)(segF + (size_t)yn * WW);
            #pragma unroll
            for (int i = 0; i < 8; ++i) {
                dv[i] = __ldcs(&dr[i * 32 + lane]);
                fv[i] = __ldcs(&fr[i * 32 + lane]);
            }
        }

        // ---- gather: box row-sums from P ----
        const int yb = Y0 + g * RPB;
        #pragma unroll
        for (int r = 0; r < RPB; ++r) {
            const int yy = yb + r;
            if (yy >= bx0.z && yy < bx0.w) a0 += P[r][bx0.y] - P[r][bx0.x];
            if (yy >= bx1.z && yy < bx1.w) a1 += P[r][bx1.y] - P[r][bx1.x];
        }
        __syncthreads();
    }

    g_partial[blockIdx.x * NTOT + base + t] = a0;
    if (t + NT < NBOX) g_partial[blockIdx.x * NTOT + base + t + NT] = a1;
}

// ---------------------------------------------------------------------------
// Reduction: 16 chunk partials per box (L2-hot) + relu*weight + grid sum via
// last-block-done counter (deterministic fixed-order final sum).
// ---------------------------------------------------------------------------
__global__ __launch_bounds__(NT)
void reduce_kernel(const float* __restrict__ boxes,
                   const float* __restrict__ conf,
                   float* __restrict__ out) {
    const int t = threadIdx.x;
    const int i = blockIdx.x * NT + t;

    float val = 0.0f;
    if (i < NTOT) {
        float s = 0.0f;
        #pragma unroll
        for (int c = 0; c < CGROUPS; ++c)
            s += g_partial[c * NTOT + i];
        float4 bb = ((const float4*)boxes)[i];
        int4 m = box_meta(bb);
        float cf = conf[i];
        bool valid = (cf >= 0.3f) && (m.y > m.x) && (m.w > m.z);
        float area = (float)((m.w - m.z) * (m.y - m.x));
        val = valid ? fmaxf(s, 0.0f) * (cf / area) : 0.0f;
    }

    // Block reduction
    __shared__ float red[NT / 32];
    #pragma unroll
    for (int o = 16; o; o >>= 1) val += __shfl_down_sync(0xffffffffu, val, o);
    if ((t & 31) == 0) red[t >> 5] = val;
    __syncthreads();
    if (t < 32) {
        float v = (t < NT / 32) ? red[t] : 0.0f;
        #pragma unroll
        for (int o = 4; o; o >>= 1) v += __shfl_down_sync(0xffffffffu, v, o);
        if (t == 0) g_blk[blockIdx.x] = v;
    }

    // Last-block-done grid reduction
    __shared__ int amLast;
    __threadfence();
    if (t == 0) amLast = (atomicAdd(&g_ctr, 1) == gridDim.x - 1);
    __syncthreads();
    if (amLast) {
        __threadfence();
        if (t < 32) {
            float v = g_blk[t];                       // t < 32 < 38
            if (t + 32 < RED_BLOCKS) v += g_blk[t + 32];
            #pragma unroll
            for (int o = 16; o; o >>= 1) v += __shfl_down_sync(0xffffffffu, v, o);
            if (t == 0) {
                out[0] = v / (float)NTOT;
                g_ctr = 0;                            // reset for next replay
            }
        }
    }
}

extern "C" void kernel_launch(void* const* d_in, const int* in_sizes, int n_in,
                              void* d_out, int out_size) {
    const float* boxes = (const float*)d_in[0];  // (32,300,4)
    const float* conf  = (const float*)d_in[1];  // (32,300)
    const float* seg   = (const float*)d_in[2];  // (32,3,1024,1024)

    dim3 grid(CGROUPS, BATCH);
    main_kernel<<<grid, NT>>>(seg, boxes);
    reduce_kernel<<<RED_BLOCKS, NT>>>(boxes, conf, (float*)d_out);
}